// round 9
// baseline (speedup 1.0000x reference)
#include <cuda_runtime.h>
#include <math.h>
#include <stdint.h>

// Problem constants
#define NB    2048        // batch (queries)
#define NC    100000      // centres
#define ND    128         // feature dim
#define KNN   200         // neighbours
#define NCL   1000        // classes
#define GCONST 0.005f     // 1/(2*sigma^2), sigma=10

// Histogram of rel = d2 - |f|^2 over [0, HRANGE)
#define HB    192
#define HBW   0.5f
#define HRANGE 96.0f
#define CAP   1024        // candidate capacity per query (expected ~220)

// -------- device scratch (no cudaMalloc allowed) --------
static __device__ float g_d2[(size_t)NB * NC];   // 819.2 MB distance matrix
static __device__ float g_cn[NC];                // centre squared norms
static __device__ float g_fq[NB];                // feature squared norms
static __device__ int   g_hist[NB * HB];
static __device__ float g_thr[NB];               // threshold on rel
static __device__ int   g_cnt[NB];
static __device__ float g_cd2[(size_t)NB * CAP];
static __device__ int   g_cix[(size_t)NB * CAP];
static __device__ int   g_lab64;                 // 1 if labels are int64

// ---------------- K0: init + label dtype sniff ----------------
__global__ void k_init(const int* __restrict__ labw) {
    int i = blockIdx.x * blockDim.x + threadIdx.x;
    if (i < NB * HB) g_hist[i] = 0;
    if (i < NB)      g_cnt[i]  = 0;
    if (i == 0) {
        // int64 labels (< 2^31) -> every odd 32-bit word is 0.
        int any = 0;
        #pragma unroll
        for (int j = 1; j < 64; j += 2) any |= labw[j];
        g_lab64 = (any == 0) ? 1 : 0;
    }
}

// ---------------- K1: squared norms, XLA-GPU row-reduce bit pattern --------
// Per lane: ((x[l]^2 + x[l+32]^2) + x[l+64]^2) + x[l+96]^2 with SEPARATE
// mul/add roundings (XLA materializes f*f, then reduce-adds; no FMA), then
// shfl_down tree 16/8/4/2/1. Lane 0 holds the canonical result bits.
__global__ void k_sqn(const float* __restrict__ feats, const float* __restrict__ cents) {
    int warp = (blockIdx.x * blockDim.x + threadIdx.x) >> 5;
    int lane = threadIdx.x & 31;
    if (warp >= NC + NB) return;
    const float* src = (warp < NC) ? (cents + (size_t)warp * ND)
                                   : (feats + (size_t)(warp - NC) * ND);
    float x0 = src[lane], x1 = src[lane + 32], x2 = src[lane + 64], x3 = src[lane + 96];
    float s = __fmul_rn(x0, x0);
    s = __fadd_rn(s, __fmul_rn(x1, x1));
    s = __fadd_rn(s, __fmul_rn(x2, x2));
    s = __fadd_rn(s, __fmul_rn(x3, x3));
    #pragma unroll
    for (int o = 16; o; o >>= 1)
        s = __fadd_rn(s, __shfl_down_sync(0xffffffffu, s, o));
    if (lane == 0) {
        if (warp < NC) g_cn[warp] = s;
        else           g_fq[warp - NC] = s;
    }
}

// ---------------- K2: fp32 SGEMM (NT) fused with d2 epilogue ----------------
// dot accumulated as a strictly increasing-k FFMA chain (cuBLAS SGEMM order).
// Epilogue forces d2 = round(round(fq + cn) - 2*dot)  [2*dot exact].
__global__ void __launch_bounds__(256) k_gemm(const float* __restrict__ A,
                                              const float* __restrict__ Bc) {
    __shared__ float As[8][132];
    __shared__ float Bs[8][132];
    int tid = threadIdx.x;
    int tx = tid & 15, ty = tid >> 4;
    int m0 = blockIdx.y * 128;
    int n0 = blockIdx.x * 128;
    int lr = tid >> 1;             // row within tile (0..127)
    int lc = (tid & 1) * 4;        // k offset (0 or 4)

    float acc[8][8];
    #pragma unroll
    for (int i = 0; i < 8; i++)
        #pragma unroll
        for (int j = 0; j < 8; j++) acc[i][j] = 0.f;

    int gm = m0 + lr;              // always < NB
    int gn = n0 + lr;
    const float4* Ap = (const float4*)(A + (size_t)gm * ND);
    bool bok = (gn < NC);
    const float4* Bp = (const float4*)(Bc + (size_t)(bok ? gn : 0) * ND);

    for (int k0 = 0; k0 < ND; k0 += 8) {
        float4 av = Ap[(k0 + lc) >> 2];
        float4 bv = bok ? Bp[(k0 + lc) >> 2] : make_float4(0.f, 0.f, 0.f, 0.f);
        __syncthreads();
        As[lc + 0][lr] = av.x; As[lc + 1][lr] = av.y;
        As[lc + 2][lr] = av.z; As[lc + 3][lr] = av.w;
        Bs[lc + 0][lr] = bv.x; Bs[lc + 1][lr] = bv.y;
        Bs[lc + 2][lr] = bv.z; Bs[lc + 3][lr] = bv.w;
        __syncthreads();
        #pragma unroll
        for (int k = 0; k < 8; k++) {
            float ra[8], rb[8];
            *(float4*)&ra[0] = *(const float4*)&As[k][ty * 8];
            *(float4*)&ra[4] = *(const float4*)&As[k][ty * 8 + 4];
            *(float4*)&rb[0] = *(const float4*)&Bs[k][tx * 8];
            *(float4*)&rb[4] = *(const float4*)&Bs[k][tx * 8 + 4];
            #pragma unroll
            for (int i = 0; i < 8; i++)
                #pragma unroll
                for (int j = 0; j < 8; j++)
                    acc[i][j] = fmaf(ra[i], rb[j], acc[i][j]);
        }
    }

    // epilogue: d2 = (fq + cn) - 2*dot with explicit roundings
    int colb = n0 + tx * 8;
    float rcn[8];
    #pragma unroll
    for (int j = 0; j < 8; j++) rcn[j] = (colb + j < NC) ? g_cn[colb + j] : 0.f;

    #pragma unroll
    for (int i = 0; i < 8; i++) {
        int row = m0 + ty * 8 + i;
        float fq = g_fq[row];
        float* dst = g_d2 + (size_t)row * NC;
        #pragma unroll
        for (int j0 = 0; j0 < 8; j0 += 4) {
            int col = colb + j0;
            if (col < NC) {   // NC%4==0, so full float4 in-bounds when col<NC
                float4 o;
                o.x = __fadd_rn(__fadd_rn(fq, rcn[j0 + 0]), __fmul_rn(-2.0f, acc[i][j0 + 0]));
                o.y = __fadd_rn(__fadd_rn(fq, rcn[j0 + 1]), __fmul_rn(-2.0f, acc[i][j0 + 1]));
                o.z = __fadd_rn(__fadd_rn(fq, rcn[j0 + 2]), __fmul_rn(-2.0f, acc[i][j0 + 2]));
                o.w = __fadd_rn(__fadd_rn(fq, rcn[j0 + 3]), __fmul_rn(-2.0f, acc[i][j0 + 3]));
                *(float4*)(dst + col) = o;
            }
        }
    }
}

// ---------------- K3: per-query histogram of rel = d2 - fq ----------------
__global__ void k_hist() {
    __shared__ int h[HB];
    int q  = blockIdx.y;
    int c0 = blockIdx.x * (NC / 8);       // 12500-wide chunks
    for (int i = threadIdx.x; i < HB; i += 256) h[i] = 0;
    __syncthreads();
    float fq = g_fq[q];
    const float* row = g_d2 + (size_t)q * NC + c0;
    for (int i = threadIdx.x; i < NC / 8; i += 256) {
        float rel = row[i] - fq;
        if (rel < HRANGE) {
            int b = (int)(rel * 2.0f);
            if (b < 0) b = 0;
            if (b > HB - 1) b = HB - 1;
            atomicAdd(&h[b], 1);
        }
    }
    __syncthreads();
    for (int i = threadIdx.x; i < HB; i += 256)
        if (h[i]) atomicAdd(&g_hist[q * HB + i], h[i]);
}

// ---------------- K4: rank-200 threshold per query ----------------
__global__ void k_thr() {
    int q = blockIdx.x * blockDim.x + threadIdx.x;
    if (q >= NB) return;
    int cum = 0;
    float t = HRANGE;
    for (int b = 0; b < HB; b++) {
        cum += g_hist[q * HB + b];
        if (cum >= KNN) { t = (float)(b + 1) * HBW; break; }
    }
    g_thr[q] = t;
}

// ---------------- K5: collect candidates below threshold ----------------
__global__ void k_coll() {
    int q  = blockIdx.y;
    int c0 = blockIdx.x * (NC / 8);
    float fq = g_fq[q];
    float t  = g_thr[q];
    const float* row = g_d2 + (size_t)q * NC + c0;
    for (int i = threadIdx.x; i < NC / 8; i += 256) {
        float d2 = row[i];
        if (d2 - fq < t) {
            int p = atomicAdd(&g_cnt[q], 1);
            if (p < CAP) {
                g_cd2[(size_t)q * CAP + p] = d2;
                g_cix[(size_t)q * CAP + p] = c0 + i;
            }
        }
    }
}

// ---------------- K6: sort (ref fp32 bits), weight, scatter, normalize ----
__global__ void __launch_bounds__(256) k_fin(const float* __restrict__ wt,
                                             const void* __restrict__ lab,
                                             float* __restrict__ out,
                                             int out_size) {
    __shared__ float sd[CAP];
    __shared__ int   si[CAP];
    __shared__ float ws[KNN];
    __shared__ int   sl[KNN];
    __shared__ float pcl[NCL];
    __shared__ float red[256];

    int q = blockIdx.x, tid = threadIdx.x;
    int M = g_cnt[q]; if (M > CAP) M = CAP;
    int P = 256; while (P < M) P <<= 1;

    for (int i = tid; i < P; i += 256) {
        if (i < M) { sd[i] = g_cd2[(size_t)q * CAP + i]; si[i] = g_cix[(size_t)q * CAP + i]; }
        else       { sd[i] = 1e30f;                      si[i] = 0x7fffffff; }
    }
    __syncthreads();

    // bitonic ascending sort on (d2, idx) — lower index first on fp32 ties,
    // matching jax.lax.top_k stability. Canonical & deterministic.
    for (int len = 2; len <= P; len <<= 1) {
        for (int s = len >> 1; s > 0; s >>= 1) {
            for (int i = tid; i < P; i += 256) {
                int j = i ^ s;
                if (j > i) {
                    bool up = ((i & len) == 0);
                    float di = sd[i], dj = sd[j];
                    int   ii = si[i], ij = si[j];
                    bool  gt = (di > dj) || (di == dj && ii > ij);
                    if (gt == up) { sd[i] = dj; sd[j] = di; si[i] = ij; si[j] = ii; }
                }
            }
            __syncthreads();
        }
    }

    int Ke = (M < KNN) ? M : KNN;
    int is64 = g_lab64;
    for (int j = tid; j < Ke; j += 256) {
        float d2 = sd[j]; if (d2 < 0.f) d2 = 0.f;   // ref: maximum(., 0)
        int ix = si[j];
        int lb = is64 ? (int)((const long long*)lab)[ix] : ((const int*)lab)[ix];
        ws[j] = expf(__fmul_rn(-d2, GCONST)) * expf(wt[ix]);
        sl[j] = lb;
    }
    __syncthreads();

    // deterministic class-major accumulation (no float atomics)
    float partial = 0.f;
    for (int c = tid; c < NCL; c += 256) {
        float p = 0.f;
        for (int j = 0; j < Ke; j++)
            if (sl[j] == c) p += ws[j];
        if (p == 0.f) p = 1e-10f;
        pcl[c] = p;
        partial += p;
    }
    red[tid] = partial;
    __syncthreads();
    #pragma unroll
    for (int o = 128; o; o >>= 1) {
        if (tid < o) red[tid] += red[tid + o];
        __syncthreads();
    }
    float S = red[0];

    for (int c = tid; c < NCL; c += 256) {
        float pn = pcl[c] / S;
        size_t o1 = (size_t)q * NCL + c;                 // log(p) block first
        size_t o2 = (size_t)NB * NCL + o1;               // then p block
        if (o1 < (size_t)out_size) out[o1] = logf(pn);
        if (o2 < (size_t)out_size) out[o2] = pn;
    }
}

// ---------------- launch ----------------
extern "C" void kernel_launch(void* const* d_in, const int* in_sizes, int n_in,
                              void* d_out, int out_size) {
    const float* feats = (const float*)d_in[0];   // [2048,128]
    const float* cents = (const float*)d_in[1];   // [100000,128]
    const float* wt    = (const float*)d_in[2];   // [100000]
    const void*  lab   = d_in[3];                 // [100000] int32 or int64

    k_init<<<(NB * HB + 255) / 256, 256>>>((const int*)lab);
    k_sqn<<<((NC + NB) * 32 + 255) / 256, 256>>>(feats, cents);
    k_gemm<<<dim3((NC + 127) / 128, NB / 128), 256>>>(feats, cents);
    k_hist<<<dim3(8, NB), 256>>>();
    k_thr<<<(NB + 255) / 256, 256>>>();
    k_coll<<<dim3(8, NB), 256>>>();
    k_fin<<<NB, 256>>>(wt, lab, (float*)d_out, out_size);
}